// round 1
// baseline (speedup 1.0000x reference)
#include <cuda_runtime.h>

#define B_DIM 16
#define C_DIM 64
#define K_DIM 207
#define L_DIM 64
#define KL 13248          // K_DIM * L_DIM
#define CKL (C_DIM * KL)  // 847872
#define KK2 42849         // K_DIM * K_DIM
#define CLDIM 4096        // C_DIM * L_DIM

// Scratch (device globals: allocation-free per harness rules)
__device__ float g_A2[B_DIM][2][KK2];                 // A0^2, A1^2   (~5.5 MB)
__device__ float g_G[B_DIM][4][K_DIM][CLDIM];         // diffused features (~217 MB)

// ---------- packed f32x2 helpers (sm_100+ PTX) ----------
__device__ __forceinline__ unsigned long long pack2(float lo, float hi) {
    unsigned long long r;
    asm("mov.b64 %0, {%1, %2};" : "=l"(r) : "f"(lo), "f"(hi));
    return r;
}
__device__ __forceinline__ void fma2(unsigned long long& d, unsigned long long a,
                                     unsigned long long b) {
    asm("fma.rn.f32x2 %0, %1, %2, %0;" : "+l"(d) : "l"(a), "l"(b));
}
__device__ __forceinline__ float2 unpack2(unsigned long long v) {
    float2 f;
    asm("mov.b64 {%0, %1}, %2;" : "=f"(f.x), "=f"(f.y) : "l"(v));
    return f;
}

// ---------- shared 64x64 microkernel: 4(j) x 4(l) per thread, 16-k chunk ----------
// As: [16][68] transposed ([k][j], padded stride 68 -> <=2-way store conflicts,
//     16B-aligned float4 reads). Bs: [16][64] ([k][l], conflict-free).
__device__ __forceinline__ void mm_tile(const float* __restrict__ As,
                                        const float* __restrict__ Bs,
                                        unsigned long long (&acc)[4][2],
                                        int ty, int tx) {
#pragma unroll
    for (int kk = 0; kk < 16; ++kk) {
        float4 av = *(const float4*)(As + kk * 68 + ty * 4);
        float4 bv = *(const float4*)(Bs + kk * 64 + tx * 4);
        unsigned long long b01 = pack2(bv.x, bv.y);
        unsigned long long b23 = pack2(bv.z, bv.w);
        unsigned long long a;
        a = pack2(av.x, av.x); fma2(acc[0][0], a, b01); fma2(acc[0][1], a, b23);
        a = pack2(av.y, av.y); fma2(acc[1][0], a, b01); fma2(acc[1][1], a, b23);
        a = pack2(av.z, av.z); fma2(acc[2][0], a, b01); fma2(acc[2][1], a, b23);
        a = pack2(av.w, av.w); fma2(acc[3][0], a, b01); fma2(acc[3][1], a, b23);
    }
}

// ---------- kernel 1: A^2 per (batch, support) ----------
__global__ __launch_bounds__(256) void square_kernel(const float* __restrict__ a0,
                                                     const float* __restrict__ a1) {
    __shared__ float As[16 * 68];
    __shared__ float Bs[16 * 64];
    int bz = blockIdx.z;
    int b = bz >> 1, s = bz & 1;
    const float* A = (s ? a1 : a0) + b * KK2;
    float* out = g_A2[b][s];
    int row0 = blockIdx.x * 64;
    int col0 = blockIdx.y * 64;

    int t = threadIdx.x;
    int tx = t & 15, ty = t >> 4;
    int la_k = t & 15, la_j = t >> 4;
    int lb_l = t & 63, lb_k = t >> 6;

    unsigned long long zz = pack2(0.f, 0.f);
    unsigned long long acc[4][2];
#pragma unroll
    for (int u = 0; u < 4; ++u) { acc[u][0] = zz; acc[u][1] = zz; }

    for (int k0 = 0; k0 < K_DIM; k0 += 16) {
        __syncthreads();
#pragma unroll
        for (int p = 0; p < 4; ++p) {
            int j = la_j + p * 16;
            int gj = row0 + j, gk = k0 + la_k;
            float v = (gj < K_DIM && gk < K_DIM) ? A[gj * K_DIM + gk] : 0.f;
            As[la_k * 68 + j] = v;
        }
#pragma unroll
        for (int p = 0; p < 4; ++p) {
            int kk = lb_k + p * 4;
            int gk = k0 + kk, gc = col0 + lb_l;
            float v = (gk < K_DIM && gc < K_DIM) ? A[gk * K_DIM + gc] : 0.f;
            Bs[kk * 64 + lb_l] = v;
        }
        __syncthreads();
        mm_tile(As, Bs, acc, ty, tx);
    }

#pragma unroll
    for (int u = 0; u < 4; ++u) {
        int gj = row0 + ty * 4 + u;
        if (gj < K_DIM) {
            float2 p01 = unpack2(acc[u][0]);
            float2 p23 = unpack2(acc[u][1]);
            float vals[4] = {p01.x, p01.y, p23.x, p23.y};
#pragma unroll
            for (int v = 0; v < 4; ++v) {
                int gc = col0 + tx * 4 + v;
                if (gc < K_DIM) out[gj * K_DIM + gc] = vals[v];
            }
        }
    }
}

// ---------- kernel 2: G[b][s] = A_s[b] (207x207) @ X[b] (207 x (c,l)) ----------
// grid: (c=64, jtile=4, b*4+s=64)
__global__ __launch_bounds__(256) void diffuse_kernel(const float* __restrict__ x,
                                                      const float* __restrict__ a0,
                                                      const float* __restrict__ a1) {
    __shared__ float As[16 * 68];
    __shared__ float Bs[16 * 64];
    int c = blockIdx.x;
    int row0 = blockIdx.y * 64;
    int bz = blockIdx.z;
    int b = bz >> 2, s = bz & 3;

    const float* A;
    if (s == 0)      A = a0 + b * KK2;
    else if (s == 1) A = g_A2[b][0];
    else if (s == 2) A = a1 + b * KK2;
    else             A = g_A2[b][1];

    const float* X = x + b * CKL + c * KL;          // [k][l], ld = 64
    float* outp = &g_G[b][s][0][0] + c * 64;        // out[j*4096 + l]

    int t = threadIdx.x;
    int tx = t & 15, ty = t >> 4;
    int la_k = t & 15, la_j = t >> 4;
    int lb_l = t & 63, lb_k = t >> 6;

    unsigned long long zz = pack2(0.f, 0.f);
    unsigned long long acc[4][2];
#pragma unroll
    for (int u = 0; u < 4; ++u) { acc[u][0] = zz; acc[u][1] = zz; }

    for (int k0 = 0; k0 < K_DIM; k0 += 16) {
        __syncthreads();
#pragma unroll
        for (int p = 0; p < 4; ++p) {
            int j = la_j + p * 16;
            int gj = row0 + j, gk = k0 + la_k;
            float v = (gj < K_DIM && gk < K_DIM) ? A[gj * K_DIM + gk] : 0.f;
            As[la_k * 68 + j] = v;
        }
#pragma unroll
        for (int p = 0; p < 4; ++p) {
            int kk = lb_k + p * 4;
            int gk = k0 + kk;
            float v = (gk < K_DIM) ? X[gk * 64 + lb_l] : 0.f;
            Bs[kk * 64 + lb_l] = v;
        }
        __syncthreads();
        mm_tile(As, Bs, acc, ty, tx);
    }

#pragma unroll
    for (int u = 0; u < 4; ++u) {
        int gj = row0 + ty * 4 + u;
        if (gj < K_DIM) {
            float2 p01 = unpack2(acc[u][0]);
            float2 p23 = unpack2(acc[u][1]);
            float4 ov = make_float4(p01.x, p01.y, p23.x, p23.y);
            *(float4*)(outp + gj * CLDIM + tx * 4) = ov;
        }
    }
}

// ---------- kernel 3: y[b] = W (64x320) @ [x;G] (320 x (j,l)) + bias ----------
// grid: (j=207, b=16)
__global__ __launch_bounds__(256) void conv_kernel(const float* __restrict__ x,
                                                   const float* __restrict__ W,
                                                   const float* __restrict__ bias,
                                                   float* __restrict__ y) {
    __shared__ float As[16 * 68];
    __shared__ float Bs[16 * 64];
    int j = blockIdx.x;
    int b = blockIdx.y;

    int t = threadIdx.x;
    int tx = t & 15, ty = t >> 4;
    int la_k = t & 15, la_j = t >> 4;
    int lb_l = t & 63, lb_k = t >> 6;

    unsigned long long acc[4][2];
#pragma unroll
    for (int u = 0; u < 4; ++u) {
        float bv = bias[ty * 4 + u];
        acc[u][0] = pack2(bv, bv);
        acc[u][1] = pack2(bv, bv);
    }

    for (int i0 = 0; i0 < 320; i0 += 16) {
        __syncthreads();
#pragma unroll
        for (int p = 0; p < 4; ++p) {
            int o = la_j + p * 16;
            As[la_k * 68 + o] = W[o * 320 + i0 + la_k];
        }
#pragma unroll
        for (int p = 0; p < 4; ++p) {
            int ii = lb_k + p * 4;
            int i = i0 + ii;
            int cc = i & 63;
            int sel = i >> 6;
            const float* rp = (sel == 0) ? (x + b * CKL + cc * KL + j * 64)
                                         : (&g_G[b][sel - 1][j][cc * 64]);
            Bs[ii * 64 + lb_l] = rp[lb_l];
        }
        __syncthreads();
        mm_tile(As, Bs, acc, ty, tx);
    }

    float* outp = y + b * CKL + j * 64;
#pragma unroll
    for (int u = 0; u < 4; ++u) {
        int o = ty * 4 + u;
        float2 p01 = unpack2(acc[u][0]);
        float2 p23 = unpack2(acc[u][1]);
        float4 ov = make_float4(p01.x, p01.y, p23.x, p23.y);
        *(float4*)(outp + o * KL + tx * 4) = ov;
    }
}

extern "C" void kernel_launch(void* const* d_in, const int* in_sizes, int n_in,
                              void* d_out, int out_size) {
    const float* x    = (const float*)d_in[0];   // (16, 64, 13248)
    const float* a0   = (const float*)d_in[1];   // (16, 207, 207)
    const float* a1   = (const float*)d_in[2];   // (16, 207, 207)
    const float* W    = (const float*)d_in[3];   // (64, 320)
    const float* bias = (const float*)d_in[4];   // (64,)
    float* y = (float*)d_out;                    // (16, 64, 13248)

    dim3 blk(256);
    square_kernel<<<dim3(4, 4, 32), blk>>>(a0, a1);
    diffuse_kernel<<<dim3(64, 4, 64), blk>>>(x, a0, a1);
    conv_kernel<<<dim3(207, 16), blk>>>(x, W, bias, y);
}